// round 15
// baseline (speedup 1.0000x reference)
#include <cuda_runtime.h>
#include <cuda_fp16.h>
#include <cstdint>

#define HIDDEN   2048
#define SEQ      4096
#define NTOK     16384          // B*S = 4*4096
#define MODULUS  65535LL
#define GATE_BIAS (-4.0f)

// -------- static scratch (no dynamic allocation allowed) --------
__device__ __half g_mem_h[(size_t)NTOK * HIDDEN];        // gathered rows (fp16)
__device__ __half g_w_h  [(size_t)2 * HIDDEN * HIDDEN];  // fp16 Wk|Wv
__device__ __half g_val_h[(size_t)NTOK * HIDDEN];        // Wv out (pre-norm, fp16)
__device__ float  gS1[NTOK];     // sum k^2 per token
__device__ float  gS2[NTOK];     // sum v^2 per token
__device__ float  gS3[NTOK];     // sum h*kw*k per token
__device__ float  gG [NTOK];     // sigmoid(logit) * rv per token

// normalized hash params (always int64 semantics of the reference)
__device__ long long n_hm2[8];
__device__ long long n_ho2[4];
__device__ long long n_hm3[12];
__device__ long long n_ho3[4];
__device__ int       g_ids_is32;

// ============================================================================
// Kernel 0: zero accumulators (all threads) + normalize params (thread 0).
// ============================================================================
__global__ void k_norm(const int* __restrict__ hm2, const int* __restrict__ ho2,
                       const int* __restrict__ hm3, const int* __restrict__ ho3,
                       const int* __restrict__ ids)
{
    const int i = blockIdx.x * 256 + threadIdx.x;
    gS1[i] = 0.f; gS2[i] = 0.f; gS3[i] = 0.f;

    if (i == 0) {
        const bool p64 = (hm2[1] == 0) && (hm2[3] == 0) && (hm2[5] == 0) && (hm2[7] == 0);
        if (p64) {
            const long long* h2 = (const long long*)hm2;
            const long long* o2 = (const long long*)ho2;
            const long long* h3 = (const long long*)hm3;
            const long long* o3 = (const long long*)ho3;
            for (int j = 0; j < 8;  j++) n_hm2[j] = h2[j];
            for (int j = 0; j < 4;  j++) n_ho2[j] = o2[j];
            for (int j = 0; j < 12; j++) n_hm3[j] = h3[j];
            for (int j = 0; j < 4;  j++) n_ho3[j] = o3[j];
        } else {
            for (int j = 0; j < 8;  j++) n_hm2[j] = (long long)(unsigned int)hm2[j];
            for (int j = 0; j < 4;  j++) n_ho2[j] = (long long)(unsigned int)ho2[j];
            for (int j = 0; j < 12; j++) n_hm3[j] = (long long)(unsigned int)hm3[j];
            for (int j = 0; j < 4;  j++) n_ho3[j] = (long long)(unsigned int)ho3[j];
        }
        bool i64 = true;
        for (int j = 1; j < 64; j += 2) {
            if (ids[j] != 0) { i64 = false; break; }
        }
        g_ids_is32 = i64 ? 0 : 1;
    }
}

// ============================================================================
// Kernel 0b: fp16-round Wk|Wv into g_w_h (half2 stores).
// ============================================================================
__global__ void k_roundW(const float* __restrict__ Wk, const float* __restrict__ Wv)
{
    size_t i = (size_t)blockIdx.x * 256 + threadIdx.x;   // pair index
    float2 a = *(const float2*)(Wk + 2 * i);
    float2 b = *(const float2*)(Wv + 2 * i);
    *(__half2*)(g_w_h + 2 * i) = __floats2half2_rn(a.x, a.y);
    *(__half2*)(g_w_h + (size_t)HIDDEN * HIDDEN + 2 * i) = __floats2half2_rn(b.x, b.y);
}

// ============================================================================
// Kernel 1: n-gram hashing + table gather (fp16 output, half2 stores).
// ============================================================================
__global__ void k_hash_gather(const void* __restrict__ ids_raw,
                              const float* __restrict__ tables)
{
    const int tok = blockIdx.x;
    const int tid = threadIdx.x;          // 0..127
    const int b = tok >> 12;
    const int s = tok & (SEQ - 1);

    __shared__ int sh_id[8];
    if (tid < 8) {
        const int head = tid & 3;
        const int ng   = tid >> 2;
        const int is32 = g_ids_is32;
        const long long* row64 = (const long long*)ids_raw + (size_t)b * SEQ;
        const int*       row32 = (const int*)      ids_raw + (size_t)b * SEQ;
        #define IDAT(x) (is32 ? (long long)row32[(x)] : row64[(x)])
        long long idv = 0;
        if (ng == 0) {
            if (s >= 1) {
                long long mix = (IDAT(s - 1) * n_hm2[head * 2 + 0])
                              ^ (IDAT(s)     * n_hm2[head * 2 + 1]);
                idv = (mix + n_ho2[head]) % MODULUS + 1;
            }
        } else {
            if (s >= 2) {
                long long mix = (IDAT(s - 2) * n_hm3[head * 3 + 0])
                              ^ (IDAT(s - 1) * n_hm3[head * 3 + 1])
                              ^ (IDAT(s)     * n_hm3[head * 3 + 2]);
                idv = (mix + n_ho3[head]) % MODULUS + 1;
            }
        }
        #undef IDAT
        if (idv < 0) idv = 0;
        if (idv > 65535) idv = 65535;
        sh_id[tid] = (int)idv;
    }
    __syncthreads();

    __half* dst = g_mem_h + (size_t)tok * HIDDEN;
#pragma unroll
    for (int h = 0; h < 8; h++) {
        size_t src = ((size_t)h * 65536 + (size_t)sh_id[h]) * 256 + 2 * tid;
        float2 v = *(const float2*)(tables + src);
        *(__half2*)(dst + h * 256 + 2 * tid) = __floats2half2_rn(v.x, v.y);
    }
}

// ============================================================================
// Kernel 2: fused dual GEMM  C = memory @ W^T, fp16 mma.sync m16n8k16.
// CTA tile 128x128, 8 warps @ 64x32, BK=64, 3-stage cp.async, 2 CTAs/SM.
// All shared addresses = 8 hoisted base registers + compile-time immediates
// (stage/mt/p offsets fold into LDSM/STS immediate fields); cp.async sources
// are 2 running pointers advanced by BK per k-tile.
// ============================================================================
#define BM 128
#define BN 128
#define BK 64
#define STG_A (BM * BK * 2)       // 16384 B
#define STG_BYTES (2 * STG_A)     // 32768 B (A then B)
#define GSMEM (3 * STG_BYTES)     // 98304 B
#define NST 32                    // HIDDEN / BK

__device__ __forceinline__ void cp16g(uint32_t smem_dst, const void* gsrc) {
    asm volatile("cp.async.cg.shared.global [%0], [%1], 16;"
                 :: "r"(smem_dst), "l"(gsrc));
}

__global__ __launch_bounds__(256, 2) void k_gemm(const float* __restrict__ hidden,
                                                 const float* __restrict__ kw)
{
    extern __shared__ __align__(128) uint8_t smbuf[];
    const uint32_t sbase = (uint32_t)__cvta_generic_to_shared(smbuf);

    const int bn  = blockIdx.x;           // 0..31 (fast)
    const int bm  = blockIdx.y;           // 0..127
    const int tid = threadIdx.x;

    const __half* A = g_mem_h + (size_t)bm * BM * HIDDEN;
    const int sel   = bn >> 4;            // 0 = Wk, 1 = Wv
    const int nloc  = (bn & 15) * BN;
    const __half* Bg = g_w_h + (size_t)sel * HIDDEN * HIDDEN + (size_t)nloc * HIDDEN;

    const int warp = tid >> 5;
    const int lane = tid & 31;
    const int wm = (warp & 1) * 64;
    const int wn = (warp >> 1) * 32;
    const int g  = lane >> 2;
    const int c  = lane & 3;
    const int lrow = (lane & 7) + ((lane >> 3) & 1) * 8;
    const int lch  = lane >> 4;            // 0/1
    const int sr   = lane & 7;

    // ---- copy slots ----
    const int r0 = tid >> 3;               // 0..31
    const int ch = tid & 7;                // 0..7
    const uint32_t scoff = sbase + r0 * 128 + ((ch ^ (r0 & 7)) << 4);
    const __half* pa0 = A  + (size_t)r0 * HIDDEN + ch * 8;
    const __half* pb0 = Bg + (size_t)r0 * HIDDEN + ch * 8;

    // ---- hoisted fragment base addresses (stage-0; stage/mt/p are imm) ----
    uint32_t aaddr[4], baddr[4];
#pragma unroll
    for (int ks = 0; ks < 4; ks++) {
        const uint32_t xk = (uint32_t)(((ks * 2 + lch) ^ sr) << 4);
        aaddr[ks] = sbase + (uint32_t)(wm + lrow) * 128 + xk;
        baddr[ks] = sbase + STG_A + (uint32_t)(wn + lrow) * 128 + xk;
    }

    float acc[4][4][4];
#pragma unroll
    for (int mt = 0; mt < 4; mt++)
#pragma unroll
        for (int nt = 0; nt < 4; nt++)
#pragma unroll
            for (int i = 0; i < 4; i++) acc[mt][nt][i] = 0.f;

    // ---- prologue: stages 0, 1 ----
#pragma unroll
    for (int st = 0; st < 2; st++) {
#pragma unroll
        for (int j = 0; j < 4; j++) {
            cp16g(scoff + st * STG_BYTES + j * 4096,
                  pa0 + j * (32 * HIDDEN) + st * BK);
            cp16g(scoff + st * STG_BYTES + STG_A + j * 4096,
                  pb0 + j * (32 * HIDDEN) + st * BK);
        }
        asm volatile("cp.async.commit_group;" ::: "memory");
    }

    // running prefetch source pointers (track tile t+2)
    const __half* pat = pa0 + 2 * BK;
    const __half* pbt = pb0 + 2 * BK;

#define GEMM_BODY(T, S)                                                        \
    do {                                                                       \
        asm volatile("cp.async.wait_group 1;" ::: "memory");                   \
        __syncthreads();                                                       \
        if ((T) + 2 < NST) {                                                   \
            _Pragma("unroll")                                                  \
            for (int j = 0; j < 4; j++) {                                      \
                cp16g(scoff + (((S) + 2) % 3) * STG_BYTES + j * 4096,          \
                      pat + j * (32 * HIDDEN));                                \
                cp16g(scoff + (((S) + 2) % 3) * STG_BYTES + STG_A + j * 4096,  \
                      pbt + j * (32 * HIDDEN));                                \
            }                                                                  \
        }                                                                      \
        asm volatile("cp.async.commit_group;" ::: "memory");                   \
        pat += BK; pbt += BK;                                                  \
        {                                                                      \
            _Pragma("unroll")                                                  \
            for (int ks = 0; ks < 4; ks++) {                                   \
                uint32_t af[4][4], bf[4][2];                                   \
                _Pragma("unroll")                                              \
                for (int mt = 0; mt < 4; mt++)                                 \
                    asm volatile(                                              \
                        "ldmatrix.sync.aligned.m8n8.x4.shared.b16 "            \
                        "{%0,%1,%2,%3}, [%4];"                                 \
                        : "=r"(af[mt][0]), "=r"(af[mt][1]),                    \
                          "=r"(af[mt][2]), "=r"(af[mt][3])                     \
                        : "r"(aaddr[ks] + ((S) * STG_BYTES + mt * 2048)));     \
                _Pragma("unroll")                                              \
                for (int p = 0; p < 2; p++) {                                  \
                    uint32_t t0, t1, t2, t3;                                   \
                    asm volatile(                                              \
                        "ldmatrix.sync.aligned.m8n8.x4.shared.b16 "            \
                        "{%0,%1,%2,%3}, [%4];"                                 \
                        : "=r"(t0), "=r"(t1), "=r"(t2), "=r"(t3)               \
                        : "r"(baddr[ks] + ((S) * STG_BYTES + p * 2048)));      \
                    bf[2 * p][0]     = t0; bf[2 * p][1]     = t2;              \
                    bf[2 * p + 1][0] = t1; bf[2 * p + 1][1] = t3;              \
                }                                                              \
                _Pragma("unroll")                                              \
                for (int mt = 0; mt < 4; mt++)                                 \
                    _Pragma("unroll")                                          \
                    for (int nt = 0; nt < 4; nt++)                             \
                        asm volatile(                                          \
                            "mma.sync.aligned.m16n8k16.row.col.f32.f16.f16.f32 " \
                            "{%0,%1,%2,%3},{%4,%5,%6,%7},{%8,%9},{%0,%1,%2,%3};" \
                            : "+f"(acc[mt][nt][0]), "+f"(acc[mt][nt][1]),      \
                              "+f"(acc[mt][nt][2]), "+f"(acc[mt][nt][3])       \
                            : "r"(af[mt][0]), "r"(af[mt][1]),                  \
                              "r"(af[mt][2]), "r"(af[mt][3]),                  \
                              "r"(bf[nt][0]), "r"(bf[nt][1]));                 \
            }                                                                  \
        }                                                                      \
    } while (0)

    for (int t = 0; t < 30; t += 3) {
        GEMM_BODY(t,     0);
        GEMM_BODY(t + 1, 1);
        GEMM_BODY(t + 2, 2);
    }
    GEMM_BODY(30, 0);
    GEMM_BODY(31, 1);

#undef GEMM_BODY

    // ---- drain async copies; smem is reused for reductions below ----
    asm volatile("cp.async.wait_group 0;" ::: "memory");
    __syncthreads();

    float* smr = (float*)smbuf;           // partial sums
    const int wgrp = warp >> 1;           // wn / 32

    if (sel == 0) {
        // ---- key blocks: reduce S1 = k^2, S3 = h*kw*k ; no C store ----
        for (int i = tid; i < 1024; i += 256) smr[i] = 0.f;
        __syncthreads();
        const float* Hbase = hidden + (size_t)bm * BM * HIDDEN + nloc;
        const float* kwb   = kw + nloc;
#pragma unroll
        for (int mt = 0; mt < 4; mt++) {
            const int rA = wm + mt * 16 + g, rB = rA + 8;
            float s1a = 0.f, s3a = 0.f, s1b = 0.f, s3b = 0.f;
#pragma unroll
            for (int nt = 0; nt < 4; nt++) {
                const int cc = wn + nt * 8 + c * 2;
                float2 wk2 = *(const float2*)(kwb + cc);
                float2 hA  = *(const float2*)(Hbase + (size_t)rA * HIDDEN + cc);
                float2 hB  = *(const float2*)(Hbase + (size_t)rB * HIDDEN + cc);
                s1a += acc[mt][nt][0] * acc[mt][nt][0] + acc[mt][nt][1] * acc[mt][nt][1];
                s3a += hA.x * wk2.x * acc[mt][nt][0] + hA.y * wk2.y * acc[mt][nt][1];
                s1b += acc[mt][nt][2] * acc[mt][nt][2] + acc[mt][nt][3] * acc[mt][nt][3];
                s3b += hB.x * wk2.x * acc[mt][nt][2] + hB.y * wk2.y * acc[mt][nt][3];
            }
#pragma unroll
            for (int o = 1; o <= 2; o <<= 1) {
                s1a += __shfl_xor_sync(0xffffffffu, s1a, o);
                s3a += __shfl_xor_sync(0xffffffffu, s3a, o);
                s1b += __shfl_xor_sync(0xffffffffu, s1b, o);
                s3b += __shfl_xor_sync(0xffffffffu, s3b, o);
            }
            if (c == 0) {
                smr[rA * 4 + wgrp]       = s1a;
                smr[512 + rA * 4 + wgrp] = s3a;
                smr[rB * 4 + wgrp]       = s1b;
                smr[512 + rB * 4 + wgrp] = s3b;
            }
        }
        __syncthreads();
        if (tid < 128) {
            float v1 = smr[tid * 4] + smr[tid * 4 + 1] + smr[tid * 4 + 2] + smr[tid * 4 + 3];
            float v3 = smr[512 + tid * 4] + smr[512 + tid * 4 + 1]
                     + smr[512 + tid * 4 + 2] + smr[512 + tid * 4 + 3];
            atomicAdd(&gS1[bm * BM + tid], v1);
            atomicAdd(&gS3[bm * BM + tid], v3);
        }
    } else {
        // ---- val blocks: store C (fp16) and reduce S2 = v^2 ----
        __half* Cg = g_val_h + (size_t)bm * BM * HIDDEN + nloc;
        for (int i = tid; i < 512; i += 256) smr[i] = 0.f;
        __syncthreads();
#pragma unroll
        for (int mt = 0; mt < 4; mt++) {
            const int rA = wm + mt * 16 + g, rB = rA + 8;
            float s2a = 0.f, s2b = 0.f;
#pragma unroll
            for (int nt = 0; nt < 4; nt++) {
                const int cc = wn + nt * 8 + c * 2;
                *(__half2*)(Cg + (size_t)rA * HIDDEN + cc) =
                    __floats2half2_rn(acc[mt][nt][0], acc[mt][nt][1]);
                *(__half2*)(Cg + (size_t)rB * HIDDEN + cc) =
                    __floats2half2_rn(acc[mt][nt][2], acc[mt][nt][3]);
                s2a += acc[mt][nt][0] * acc[mt][nt][0] + acc[mt][nt][1] * acc[mt][nt][1];
                s2b += acc[mt][nt][2] * acc[mt][nt][2] + acc[mt][nt][3] * acc[mt][nt][3];
            }
#pragma unroll
            for (int o = 1; o <= 2; o <<= 1) {
                s2a += __shfl_xor_sync(0xffffffffu, s2a, o);
                s2b += __shfl_xor_sync(0xffffffffu, s2b, o);
            }
            if (c == 0) {
                smr[rA * 4 + wgrp] = s2a;
                smr[rB * 4 + wgrp] = s2b;
            }
        }
        __syncthreads();
        if (tid < 128) {
            float v2 = smr[tid * 4] + smr[tid * 4 + 1] + smr[tid * 4 + 2] + smr[tid * 4 + 3];
            atomicAdd(&gS2[bm * BM + tid], v2);
        }
    }
}

// ============================================================================
// Kernel 3: per-token gate factor  G = sigmoid(logit) * rv
// ============================================================================
__global__ void k_gfac()
{
    const int tok = blockIdx.x * 256 + threadIdx.x;
    const float S1 = gS1[tok], S2 = gS2[tok], S3 = gS3[tok];
    const float rk = rsqrtf(S1 * (1.0f / HIDDEN) + 1e-6f);
    const float rv = rsqrtf(S2 * (1.0f / HIDDEN) + 1e-6f);
    const float logit = S3 * rk * (1.0f / 45.254833995939045f) + GATE_BIAS;
    gG[tok] = rv / (1.0f + expf(-logit));
}

// ============================================================================
// Kernel 4: fused gating + causal conv (K=3) + residual, token-tiled.
// Block = 256 threads x 4 channels x 8 consecutive tokens; previous gated
// values carried in registers; float4 weight/out, uint2 half reads.
// ============================================================================
__global__ void k_conv2(const float* __restrict__ vw,
                        const float* __restrict__ conv_w,
                        float* __restrict__ out)
{
    const int d  = (blockIdx.x * 256 + threadIdx.x) * 4;   // channel quad
    const int t0 = blockIdx.y * 8;            // 8-aligned, SEQ divisible by 8
    const int s0 = t0 & (SEQ - 1);

    // 12 conv weights for 4 channels: [d*3 .. d*3+11], 16B-aligned
    const float4 cw0 = *(const float4*)(conv_w + d * 3);
    const float4 cw1 = *(const float4*)(conv_w + d * 3 + 4);
    const float4 cw2 = *(const float4*)(conv_w + d * 3 + 8);
    // per-channel (w0,w1,w2):
    const float w0x = cw0.x, w1x = cw0.y, w2x = cw0.z;
    const float w0y = cw0.w, w1y = cw1.x, w2y = cw1.y;
    const float w0z = cw1.z, w1z = cw1.w, w2z = cw2.x;
    const float w0w = cw2.y, w1w = cw2.z, w2w = cw2.w;
    const float4 vw4 = *(const float4*)(vw + d);

    const size_t base = (size_t)t0 * HIDDEN + d;

    float4 gm1 = make_float4(0.f, 0.f, 0.f, 0.f);
    float4 gm2 = make_float4(0.f, 0.f, 0.f, 0.f);
    if (s0 >= 1) {
        const __half2* p = (const __half2*)(g_val_h + base - HIDDEN);
        float2 a = __half22float2(p[0]), b = __half22float2(p[1]);
        const float G = gG[t0 - 1];
        gm1 = make_float4(G * a.x, G * a.y, G * b.x, G * b.y);
    }
    if (s0 >= 2) {
        const __half2* p = (const __half2*)(g_val_h + base - 2 * HIDDEN);
        float2 a = __half22float2(p[0]), b = __half22float2(p[1]);
        const float G = gG[t0 - 2];
        gm2 = make_float4(G * a.x, G * a.y, G * b.x, G * b.y);
    }

#pragma unroll
    for (int i = 0; i < 8; i++) {
        const __half2* p = (const __half2*)(g_val_h + base + (size_t)i * HIDDEN);
        float2 a = __half22float2(p[0]), b = __half22float2(p[1]);
        const float G = gG[t0 + i];
        const float4 gc = make_float4(G * a.x, G * a.y, G * b.x, G * b.y);
        float4 o;
        o.x = vw4.x * ((1.0f + w2x) * gc.x + w1x * gm1.x + w0x * gm2.x);
        o.y = vw4.y * ((1.0f + w2y) * gc.y + w1y * gm1.y + w0y * gm2.y);
        o.z = vw4.z * ((1.0f + w2z) * gc.z + w1z * gm1.z + w0z * gm2.z);
        o.w = vw4.w * ((1.0f + w2w) * gc.w + w1w * gm1.w + w0w * gm2.w);
        *(float4*)(out + base + (size_t)i * HIDDEN) = o;
        gm2 = gm1;
        gm1 = gc;
    }
}

// ============================================================================
extern "C" void kernel_launch(void* const* d_in, const int* in_sizes, int n_in,
                              void* d_out, int out_size)
{
    const float* hidden = nullptr;
    const void*  ids    = nullptr;
    const float* tables = nullptr;
    const float* Wk = nullptr, *Wv = nullptr;
    const float* knw = nullptr, *vnw = nullptr;
    const float* convw = nullptr;
    const int*   hm2 = nullptr, *ho2 = nullptr, *hm3 = nullptr, *ho3 = nullptr;

    for (int i = 0; i < n_in; i++) {
        const int sz = in_sizes[i];
        void* p = d_in[i];
        switch (sz) {
            case 33554432:  hidden = (const float*)p; break;
            case 16384:     ids    = (const void*)p; break;
            case 134217728: tables = (const float*)p; break;
            case 4194304:   if (!Wk) Wk = (const float*)p; else Wv = (const float*)p; break;
            case 2048:      if (!knw) knw = (const float*)p; else vnw = (const float*)p; break;
            case 6144:      convw = (const float*)p; break;
            case 8:         hm2 = (const int*)p; break;
            case 12:        hm3 = (const int*)p; break;
            case 4:         if (!ho2) ho2 = (const int*)p; else ho3 = (const int*)p; break;
            default: break;
        }
    }
    float* out = (float*)d_out;

    cudaFuncSetAttribute(k_gemm, cudaFuncAttributeMaxDynamicSharedMemorySize, GSMEM);

    k_norm<<<NTOK / 256, 256>>>(hm2, ho2, hm3, ho3, (const int*)ids);
    k_roundW<<<HIDDEN * HIDDEN / 512, 256>>>(Wk, Wv);
    k_hash_gather<<<NTOK, 128>>>(ids, tables);
    k_gemm<<<dim3(32, NTOK / BM), 256, GSMEM>>>(hidden, knw);
    k_gfac<<<NTOK / 256, 256>>>();
    k_conv2<<<dim3(HIDDEN / 1024, NTOK / 8), 256>>>(vnw, convw, out);
}

// round 16
// speedup vs baseline: 1.0163x; 1.0163x over previous
#include <cuda_runtime.h>
#include <cuda_fp16.h>
#include <cstdint>

#define HIDDEN   2048
#define SEQ      4096
#define NTOK     16384          // B*S = 4*4096
#define MODULUS  65535LL
#define GATE_BIAS (-4.0f)

// -------- static scratch (no dynamic allocation allowed) --------
__device__ __half g_mem_h[(size_t)NTOK * HIDDEN];        // gathered rows (fp16)
__device__ __half g_w_h  [(size_t)2 * HIDDEN * HIDDEN];  // fp16 Wk|Wv
__device__ __half g_val_h[(size_t)NTOK * HIDDEN];        // Wv out (pre-norm, fp16)
__device__ float  gS1[NTOK];     // sum k^2 per token
__device__ float  gS2[NTOK];     // sum v^2 per token
__device__ float  gS3[NTOK];     // sum h*kw*k per token
__device__ float  gG [NTOK];     // sigmoid(logit) * rv per token

// ============================================================================
// Kernel 1 (fused prep): blocks [0, 8192): fp16-round Wk|Wv.
// Blocks [8192, 16384): hash (inline param-width detection) + gather for
// 2 tokens per block + zero the 2 tokens' gS accumulators.
// ============================================================================
__global__ void k_prep(const float* __restrict__ Wk, const float* __restrict__ Wv,
                       const void*  __restrict__ ids_raw,
                       const float* __restrict__ tables,
                       const int* __restrict__ hm2, const int* __restrict__ ho2,
                       const int* __restrict__ hm3, const int* __restrict__ ho3)
{
    const int blk = blockIdx.x;
    const int tid = threadIdx.x;          // 0..255

    if (blk < 8192) {
        // ---- roundW slice: thread handles pair i of each W ----
        size_t i = (size_t)blk * 256 + tid;
        float2 a = *(const float2*)(Wk + 2 * i);
        float2 b = *(const float2*)(Wv + 2 * i);
        *(__half2*)(g_w_h + 2 * i) = __floats2half2_rn(a.x, a.y);
        *(__half2*)(g_w_h + (size_t)HIDDEN * HIDDEN + 2 * i) = __floats2half2_rn(b.x, b.y);
        return;
    }

    // ---- hash + gather for tokens tok0, tok0+1 ----
    const int tok0 = (blk - 8192) * 2;
    __shared__ int sh_id[16];             // 8 ids per token

    if (tid < 16) {
        const int tok  = tok0 + (tid >> 3);
        const int slot = tid & 7;         // 0-3: n=2 heads, 4-7: n=3 heads
        const int b = tok >> 12;
        const int s = tok & (SEQ - 1);

        // storage-width probes (L2-cached, deterministic inputs)
        const bool p64 = (hm2[1] == 0) && (hm2[3] == 0) && (hm2[5] == 0) && (hm2[7] == 0);
        const int* iw = (const int*)ids_raw;
        const bool i64 = (iw[1] == 0) && (iw[3] == 0) && (iw[5] == 0) && (iw[7] == 0);

        const long long* row64 = (const long long*)ids_raw + (size_t)b * SEQ;
        const int*       row32 = (const int*)      ids_raw + (size_t)b * SEQ;
        #define IDAT(x) (i64 ? row64[(x)] : (long long)row32[(x)])

        long long idv = 0;
        if (slot < 4) {
            if (s >= 1) {
                long long m0, m1, off;
                if (p64) {
                    m0  = ((const long long*)hm2)[slot * 2 + 0];
                    m1  = ((const long long*)hm2)[slot * 2 + 1];
                    off = ((const long long*)ho2)[slot];
                } else {
                    m0  = (long long)(unsigned int)hm2[slot * 2 + 0];
                    m1  = (long long)(unsigned int)hm2[slot * 2 + 1];
                    off = (long long)(unsigned int)ho2[slot];
                }
                long long mix = (IDAT(s - 1) * m0) ^ (IDAT(s) * m1);
                idv = (mix + off) % MODULUS + 1;
            }
        } else {
            const int head = slot - 4;
            if (s >= 2) {
                long long m0, m1, m2, off;
                if (p64) {
                    m0  = ((const long long*)hm3)[head * 3 + 0];
                    m1  = ((const long long*)hm3)[head * 3 + 1];
                    m2  = ((const long long*)hm3)[head * 3 + 2];
                    off = ((const long long*)ho3)[head];
                } else {
                    m0  = (long long)(unsigned int)hm3[head * 3 + 0];
                    m1  = (long long)(unsigned int)hm3[head * 3 + 1];
                    m2  = (long long)(unsigned int)hm3[head * 3 + 2];
                    off = (long long)(unsigned int)ho3[head];
                }
                long long mix = (IDAT(s - 2) * m0) ^ (IDAT(s - 1) * m1) ^ (IDAT(s) * m2);
                idv = (mix + off) % MODULUS + 1;
            }
        }
        #undef IDAT
        if (idv < 0) idv = 0;
        if (idv > 65535) idv = 65535;
        sh_id[tid] = (int)idv;
    } else if (tid >= 16 && tid < 22) {
        // zero the two tokens' accumulators
        const int q = tid - 16;
        const int t = tok0 + (q >= 3 ? 1 : 0);
        const int w = (q >= 3 ? q - 3 : q);
        if (w == 0) gS1[t] = 0.f;
        else if (w == 1) gS2[t] = 0.f;
        else gS3[t] = 0.f;
    }
    __syncthreads();

    // gather: threads 0-127 -> tok0, threads 128-255 -> tok0+1
    const int tk  = tid >> 7;             // 0/1
    const int lt  = tid & 127;            // 0..127
    const int* ids8 = sh_id + tk * 8;
    __half* dst = g_mem_h + (size_t)(tok0 + tk) * HIDDEN;
#pragma unroll
    for (int h = 0; h < 8; h++) {
        size_t src = ((size_t)h * 65536 + (size_t)ids8[h]) * 256 + 2 * lt;
        float2 v = *(const float2*)(tables + src);
        *(__half2*)(dst + h * 256 + 2 * lt) = __floats2half2_rn(v.x, v.y);
    }
}

// ============================================================================
// Kernel 2: fused dual GEMM  C = memory @ W^T, fp16 mma.sync m16n8k16.
// CTA tile 128x128, 8 warps @ 64x32, BK=64, 3-stage cp.async, 2 CTAs/SM.
// Wk blocks (sel=0): no C store; reduce S1 = sum(k^2), S3 = sum(h*kw*k).
// Wv blocks (sel=1): store val (fp16) + reduce S2 = sum(v^2).
// ============================================================================
#define BM 128
#define BN 128
#define BK 64
#define STG_A (BM * BK * 2)       // 16384 B
#define STG_BYTES (2 * STG_A)     // 32768 B (A then B)
#define GSMEM (3 * STG_BYTES)     // 98304 B
#define NST 32                    // HIDDEN / BK

__device__ __forceinline__ void cp16g(uint32_t smem_dst, const void* gsrc) {
    asm volatile("cp.async.cg.shared.global [%0], [%1], 16;"
                 :: "r"(smem_dst), "l"(gsrc));
}

__global__ __launch_bounds__(256, 2) void k_gemm(const float* __restrict__ hidden,
                                                 const float* __restrict__ kw)
{
    extern __shared__ __align__(128) uint8_t smbuf[];
    const uint32_t sbase = (uint32_t)__cvta_generic_to_shared(smbuf);

    const int bn  = blockIdx.x;           // 0..31 (fast)
    const int bm  = blockIdx.y;           // 0..127
    const int tid = threadIdx.x;

    const __half* A = g_mem_h + (size_t)bm * BM * HIDDEN;
    const int sel   = bn >> 4;            // 0 = Wk, 1 = Wv
    const int nloc  = (bn & 15) * BN;
    const __half* Bg = g_w_h + (size_t)sel * HIDDEN * HIDDEN + (size_t)nloc * HIDDEN;

    const int warp = tid >> 5;
    const int lane = tid & 31;
    const int wm = (warp & 1) * 64;
    const int wn = (warp >> 1) * 32;
    const int g  = lane >> 2;
    const int c  = lane & 3;
    const int lrow = (lane & 7) + ((lane >> 3) & 1) * 8;
    const int lch  = lane >> 4;            // 0/1
    const int sr   = lane & 7;

    // ---- copy slots ----
    const int r0 = tid >> 3;               // 0..31
    const int ch = tid & 7;                // 0..7
    const uint32_t scoff = sbase + r0 * 128 + ((ch ^ (r0 & 7)) << 4);
    const __half* pa0 = A  + (size_t)r0 * HIDDEN + ch * 8;
    const __half* pb0 = Bg + (size_t)r0 * HIDDEN + ch * 8;

    // ---- hoisted fragment base addresses ----
    uint32_t aaddr[4], baddr[4];
#pragma unroll
    for (int ks = 0; ks < 4; ks++) {
        const uint32_t xk = (uint32_t)(((ks * 2 + lch) ^ sr) << 4);
        aaddr[ks] = sbase + (uint32_t)(wm + lrow) * 128 + xk;
        baddr[ks] = sbase + STG_A + (uint32_t)(wn + lrow) * 128 + xk;
    }

    float acc[4][4][4];
#pragma unroll
    for (int mt = 0; mt < 4; mt++)
#pragma unroll
        for (int nt = 0; nt < 4; nt++)
#pragma unroll
            for (int i = 0; i < 4; i++) acc[mt][nt][i] = 0.f;

    // ---- prologue: stages 0, 1 ----
#pragma unroll
    for (int st = 0; st < 2; st++) {
#pragma unroll
        for (int j = 0; j < 4; j++) {
            cp16g(scoff + st * STG_BYTES + j * 4096,
                  pa0 + j * (32 * HIDDEN) + st * BK);
            cp16g(scoff + st * STG_BYTES + STG_A + j * 4096,
                  pb0 + j * (32 * HIDDEN) + st * BK);
        }
        asm volatile("cp.async.commit_group;" ::: "memory");
    }

    // running prefetch source pointers (track tile t+2)
    const __half* pat = pa0 + 2 * BK;
    const __half* pbt = pb0 + 2 * BK;

#define GEMM_BODY(T, S)                                                        \
    do {                                                                       \
        asm volatile("cp.async.wait_group 1;" ::: "memory");                   \
        __syncthreads();                                                       \
        if ((T) + 2 < NST) {                                                   \
            _Pragma("unroll")                                                  \
            for (int j = 0; j < 4; j++) {                                      \
                cp16g(scoff + (((S) + 2) % 3) * STG_BYTES + j * 4096,          \
                      pat + j * (32 * HIDDEN));                                \
                cp16g(scoff + (((S) + 2) % 3) * STG_BYTES + STG_A + j * 4096,  \
                      pbt + j * (32 * HIDDEN));                                \
            }                                                                  \
        }                                                                      \
        asm volatile("cp.async.commit_group;" ::: "memory");                   \
        pat += BK; pbt += BK;                                                  \
        {                                                                      \
            _Pragma("unroll")                                                  \
            for (int ks = 0; ks < 4; ks++) {                                   \
                uint32_t af[4][4], bf[4][2];                                   \
                _Pragma("unroll")                                              \
                for (int mt = 0; mt < 4; mt++)                                 \
                    asm volatile(                                              \
                        "ldmatrix.sync.aligned.m8n8.x4.shared.b16 "            \
                        "{%0,%1,%2,%3}, [%4];"                                 \
                        : "=r"(af[mt][0]), "=r"(af[mt][1]),                    \
                          "=r"(af[mt][2]), "=r"(af[mt][3])                     \
                        : "r"(aaddr[ks] + ((S) * STG_BYTES + mt * 2048)));     \
                _Pragma("unroll")                                              \
                for (int p = 0; p < 2; p++) {                                  \
                    uint32_t t0, t1, t2, t3;                                   \
                    asm volatile(                                              \
                        "ldmatrix.sync.aligned.m8n8.x4.shared.b16 "            \
                        "{%0,%1,%2,%3}, [%4];"                                 \
                        : "=r"(t0), "=r"(t1), "=r"(t2), "=r"(t3)               \
                        : "r"(baddr[ks] + ((S) * STG_BYTES + p * 2048)));      \
                    bf[2 * p][0]     = t0; bf[2 * p][1]     = t2;              \
                    bf[2 * p + 1][0] = t1; bf[2 * p + 1][1] = t3;              \
                }                                                              \
                _Pragma("unroll")                                              \
                for (int mt = 0; mt < 4; mt++)                                 \
                    _Pragma("unroll")                                          \
                    for (int nt = 0; nt < 4; nt++)                             \
                        asm volatile(                                          \
                            "mma.sync.aligned.m16n8k16.row.col.f32.f16.f16.f32 " \
                            "{%0,%1,%2,%3},{%4,%5,%6,%7},{%8,%9},{%0,%1,%2,%3};" \
                            : "+f"(acc[mt][nt][0]), "+f"(acc[mt][nt][1]),      \
                              "+f"(acc[mt][nt][2]), "+f"(acc[mt][nt][3])       \
                            : "r"(af[mt][0]), "r"(af[mt][1]),                  \
                              "r"(af[mt][2]), "r"(af[mt][3]),                  \
                              "r"(bf[nt][0]), "r"(bf[nt][1]));                 \
            }                                                                  \
        }                                                                      \
    } while (0)

    for (int t = 0; t < 30; t += 3) {
        GEMM_BODY(t,     0);
        GEMM_BODY(t + 1, 1);
        GEMM_BODY(t + 2, 2);
    }
    GEMM_BODY(30, 0);
    GEMM_BODY(31, 1);

#undef GEMM_BODY

    // ---- drain async copies; smem is reused for reductions below ----
    asm volatile("cp.async.wait_group 0;" ::: "memory");
    __syncthreads();

    float* smr = (float*)smbuf;           // partial sums
    const int wgrp = warp >> 1;           // wn / 32

    if (sel == 0) {
        // ---- key blocks: reduce S1 = k^2, S3 = h*kw*k ; no C store ----
        for (int i = tid; i < 1024; i += 256) smr[i] = 0.f;
        __syncthreads();
        const float* Hbase = hidden + (size_t)bm * BM * HIDDEN + nloc;
        const float* kwb   = kw + nloc;
#pragma unroll
        for (int mt = 0; mt < 4; mt++) {
            const int rA = wm + mt * 16 + g, rB = rA + 8;
            float s1a = 0.f, s3a = 0.f, s1b = 0.f, s3b = 0.f;
#pragma unroll
            for (int nt = 0; nt < 4; nt++) {
                const int cc = wn + nt * 8 + c * 2;
                float2 wk2 = *(const float2*)(kwb + cc);
                float2 hA  = *(const float2*)(Hbase + (size_t)rA * HIDDEN + cc);
                float2 hB  = *(const float2*)(Hbase + (size_t)rB * HIDDEN + cc);
                s1a += acc[mt][nt][0] * acc[mt][nt][0] + acc[mt][nt][1] * acc[mt][nt][1];
                s3a += hA.x * wk2.x * acc[mt][nt][0] + hA.y * wk2.y * acc[mt][nt][1];
                s1b += acc[mt][nt][2] * acc[mt][nt][2] + acc[mt][nt][3] * acc[mt][nt][3];
                s3b += hB.x * wk2.x * acc[mt][nt][2] + hB.y * wk2.y * acc[mt][nt][3];
            }
#pragma unroll
            for (int o = 1; o <= 2; o <<= 1) {
                s1a += __shfl_xor_sync(0xffffffffu, s1a, o);
                s3a += __shfl_xor_sync(0xffffffffu, s3a, o);
                s1b += __shfl_xor_sync(0xffffffffu, s1b, o);
                s3b += __shfl_xor_sync(0xffffffffu, s3b, o);
            }
            if (c == 0) {
                smr[rA * 4 + wgrp]       = s1a;
                smr[512 + rA * 4 + wgrp] = s3a;
                smr[rB * 4 + wgrp]       = s1b;
                smr[512 + rB * 4 + wgrp] = s3b;
            }
        }
        __syncthreads();
        if (tid < 128) {
            float v1 = smr[tid * 4] + smr[tid * 4 + 1] + smr[tid * 4 + 2] + smr[tid * 4 + 3];
            float v3 = smr[512 + tid * 4] + smr[512 + tid * 4 + 1]
                     + smr[512 + tid * 4 + 2] + smr[512 + tid * 4 + 3];
            atomicAdd(&gS1[bm * BM + tid], v1);
            atomicAdd(&gS3[bm * BM + tid], v3);
        }
    } else {
        // ---- val blocks: store C (fp16) and reduce S2 = v^2 ----
        __half* Cg = g_val_h + (size_t)bm * BM * HIDDEN + nloc;
        for (int i = tid; i < 512; i += 256) smr[i] = 0.f;
        __syncthreads();
#pragma unroll
        for (int mt = 0; mt < 4; mt++) {
            const int rA = wm + mt * 16 + g, rB = rA + 8;
            float s2a = 0.f, s2b = 0.f;
#pragma unroll
            for (int nt = 0; nt < 4; nt++) {
                const int cc = wn + nt * 8 + c * 2;
                *(__half2*)(Cg + (size_t)rA * HIDDEN + cc) =
                    __floats2half2_rn(acc[mt][nt][0], acc[mt][nt][1]);
                *(__half2*)(Cg + (size_t)rB * HIDDEN + cc) =
                    __floats2half2_rn(acc[mt][nt][2], acc[mt][nt][3]);
                s2a += acc[mt][nt][0] * acc[mt][nt][0] + acc[mt][nt][1] * acc[mt][nt][1];
                s2b += acc[mt][nt][2] * acc[mt][nt][2] + acc[mt][nt][3] * acc[mt][nt][3];
            }
#pragma unroll
            for (int o = 1; o <= 2; o <<= 1) {
                s2a += __shfl_xor_sync(0xffffffffu, s2a, o);
                s2b += __shfl_xor_sync(0xffffffffu, s2b, o);
            }
            if (c == 0) {
                smr[rA * 4 + wgrp] = s2a;
                smr[rB * 4 + wgrp] = s2b;
            }
        }
        __syncthreads();
        if (tid < 128) {
            float v2 = smr[tid * 4] + smr[tid * 4 + 1] + smr[tid * 4 + 2] + smr[tid * 4 + 3];
            atomicAdd(&gS2[bm * BM + tid], v2);
        }
    }
}

// ============================================================================
// Kernel 3: per-token gate factor  G = sigmoid(logit) * rv
// ============================================================================
__global__ void k_gfac()
{
    const int tok = blockIdx.x * 256 + threadIdx.x;
    const float S1 = gS1[tok], S2 = gS2[tok], S3 = gS3[tok];
    const float rk = rsqrtf(S1 * (1.0f / HIDDEN) + 1e-6f);
    const float rv = rsqrtf(S2 * (1.0f / HIDDEN) + 1e-6f);
    const float logit = S3 * rk * (1.0f / 45.254833995939045f) + GATE_BIAS;
    gG[tok] = rv / (1.0f + expf(-logit));
}

// ============================================================================
// Kernel 4: fused gating + causal conv (K=3) + residual, token-tiled.
// Block = 256 threads x 2 channels x 8 consecutive tokens; previous gated
// values carried in registers (each val row read once, half2 loads).
// ============================================================================
__global__ void k_conv2(const float* __restrict__ vw,
                        const float* __restrict__ conv_w,
                        float* __restrict__ out)
{
    const int d  = (blockIdx.x * 256 + threadIdx.x) * 2;   // channel pair
    const int t0 = blockIdx.y * 8;            // 8-aligned, SEQ divisible by 8
    const int s0 = t0 & (SEQ - 1);

    const float w0x = conv_w[d * 3 + 0], w1x = conv_w[d * 3 + 1], w2x = conv_w[d * 3 + 2];
    const float w0y = conv_w[d * 3 + 3], w1y = conv_w[d * 3 + 4], w2y = conv_w[d * 3 + 5];
    const float2 vw2 = *(const float2*)(vw + d);

    const size_t base = (size_t)t0 * HIDDEN + d;
    float2 gm1 = make_float2(0.f, 0.f), gm2 = make_float2(0.f, 0.f);
    if (s0 >= 1) {
        float2 f = __half22float2(*(const __half2*)(g_val_h + base - HIDDEN));
        float G = gG[t0 - 1];
        gm1 = make_float2(G * f.x, G * f.y);
    }
    if (s0 >= 2) {
        float2 f = __half22float2(*(const __half2*)(g_val_h + base - 2 * HIDDEN));
        float G = gG[t0 - 2];
        gm2 = make_float2(G * f.x, G * f.y);
    }

#pragma unroll
    for (int i = 0; i < 8; i++) {
        float2 f = __half22float2(*(const __half2*)(g_val_h + base + (size_t)i * HIDDEN));
        const float G = gG[t0 + i];
        const float2 gc = make_float2(G * f.x, G * f.y);
        float2 o;
        o.x = vw2.x * ((1.0f + w2x) * gc.x + w1x * gm1.x + w0x * gm2.x);
        o.y = vw2.y * ((1.0f + w2y) * gc.y + w1y * gm1.y + w0y * gm2.y);
        *(float2*)(out + base + (size_t)i * HIDDEN) = o;
        gm2 = gm1;
        gm1 = gc;
    }
}

// ============================================================================
extern "C" void kernel_launch(void* const* d_in, const int* in_sizes, int n_in,
                              void* d_out, int out_size)
{
    const float* hidden = nullptr;
    const void*  ids    = nullptr;
    const float* tables = nullptr;
    const float* Wk = nullptr, *Wv = nullptr;
    const float* knw = nullptr, *vnw = nullptr;
    const float* convw = nullptr;
    const int*   hm2 = nullptr, *ho2 = nullptr, *hm3 = nullptr, *ho3 = nullptr;

    for (int i = 0; i < n_in; i++) {
        const int sz = in_sizes[i];
        void* p = d_in[i];
        switch (sz) {
            case 33554432:  hidden = (const float*)p; break;
            case 16384:     ids    = (const void*)p; break;
            case 134217728: tables = (const float*)p; break;
            case 4194304:   if (!Wk) Wk = (const float*)p; else Wv = (const float*)p; break;
            case 2048:      if (!knw) knw = (const float*)p; else vnw = (const float*)p; break;
            case 6144:      convw = (const float*)p; break;
            case 8:         hm2 = (const int*)p; break;
            case 12:        hm3 = (const int*)p; break;
            case 4:         if (!ho2) ho2 = (const int*)p; else ho3 = (const int*)p; break;
            default: break;
        }
    }
    float* out = (float*)d_out;

    cudaFuncSetAttribute(k_gemm, cudaFuncAttributeMaxDynamicSharedMemorySize, GSMEM);

    k_prep<<<16384, 256>>>(Wk, Wv, ids, tables, hm2, ho2, hm3, ho3);
    k_gemm<<<dim3(32, NTOK / BM), 256, GSMEM>>>(hidden, knw);
    k_gfac<<<NTOK / 256, 256>>>();
    k_conv2<<<dim3(HIDDEN / 512, NTOK / 8), 256>>>(vnw, convw, out);
}